// round 4
// baseline (speedup 1.0000x reference)
#include <cuda_runtime.h>
#include <math.h>

#define N_NODES 50000
#define E_EDGES 1600000
#define B_BATCH 64
#define NB (N_NODES * B_BATCH)

// Scratch: ~38.5 MB of __device__ globals (allocation-free per harness rules).
// __align__(16) is REQUIRED: these are accessed via float4 loads and
// red.global.add.v4.f32, both of which trap (err715) on <16B alignment.
__device__ __align__(16) float g_xt[NB];      // x transposed, node-major [N][64]
__device__ __align__(16) float g_msg_r[NB];   // reaction messages  [N][64]
__device__ __align__(16) float g_msg_d[NB];   // diffusion messages [N][64]
__device__ float g_col_r[N_NODES];
__device__ float g_col_d[N_NODES];

__device__ __forceinline__ void red_add_v4(float* p, float4 v) {
    unsigned long long gp;
    asm("cvta.to.global.u64 %0, %1;" : "=l"(gp) : "l"(p));
    asm volatile("red.global.add.v4.f32 [%0], {%1,%2,%3,%4};"
                 :: "l"(gp), "f"(v.x), "f"(v.y), "f"(v.z), "f"(v.w)
                 : "memory");
}

// ---------------------------------------------------------------------------
// Zero the accumulators (graph-replay safe: runs every iteration)
// ---------------------------------------------------------------------------
__global__ void zero_kernel() {
    int tid = blockIdx.x * blockDim.x + threadIdx.x;
    const int Q = NB / 4;  // float4 count per msg buffer
    float4 z = make_float4(0.f, 0.f, 0.f, 0.f);
    if (tid < Q) {
        reinterpret_cast<float4*>(g_msg_r)[tid] = z;
    } else if (tid < 2 * Q) {
        reinterpret_cast<float4*>(g_msg_d)[tid - Q] = z;
    } else if (tid < 2 * Q + N_NODES) {
        g_col_r[tid - 2 * Q] = 0.f;
    } else if (tid < 2 * Q + 2 * N_NODES) {
        g_col_d[tid - 2 * Q - N_NODES] = 0.f;
    }
}

// ---------------------------------------------------------------------------
// Transpose x [B, N] (batch-major) -> g_xt [N, 64] (node-major)
// ---------------------------------------------------------------------------
__global__ void transpose_kernel(const float* __restrict__ x) {
    __shared__ float tile[32][33];
    int v0 = blockIdx.x * 32;
    int b0 = blockIdx.y * 32;
    int tx = threadIdx.x;   // 0..31
    int ty = threadIdx.y;   // 0..7

    #pragma unroll
    for (int r = 0; r < 32; r += 8) {
        int b = b0 + ty + r;
        int v = v0 + tx;
        if (v < N_NODES)
            tile[ty + r][tx] = x[(long)b * N_NODES + v];
    }
    __syncthreads();
    #pragma unroll
    for (int r = 0; r < 32; r += 8) {
        int v = v0 + ty + r;
        int b = b0 + tx;
        if (v < N_NODES)
            g_xt[v * B_BATCH + b] = tile[tx][ty + r];
    }
}

// ---------------------------------------------------------------------------
// Edge scatter: 16 threads per edge, each handles 4 batches (float4)
//   msg_r[i][:] += w_r * xt[j][:]     col_r[j] += w_r
//   msg_d[j][:] += w_d * xt[i][:]     col_d[i] += w_d
// ---------------------------------------------------------------------------
__global__ void edge_kernel(const int* __restrict__ ei,
                            const int* __restrict__ ej,
                            const float* __restrict__ wr,
                            const float* __restrict__ wd) {
    long tid = (long)blockIdx.x * blockDim.x + threadIdx.x;
    int e = (int)(tid >> 4);
    int q = (int)(tid & 15);
    if (e >= E_EDGES) return;

    int i = ei[e];
    int j = ej[e];
    float w1 = wr[e];
    float w2 = wd[e];

    const float4* xt4 = reinterpret_cast<const float4*>(g_xt);
    float4 xj = xt4[j * 16 + q];
    float4 xi = xt4[i * 16 + q];

    float4 a = make_float4(w1 * xj.x, w1 * xj.y, w1 * xj.z, w1 * xj.w);
    red_add_v4(&g_msg_r[(i * 16 + q) * 4], a);

    float4 b = make_float4(w2 * xi.x, w2 * xi.y, w2 * xi.z, w2 * xi.w);
    red_add_v4(&g_msg_d[(j * 16 + q) * 4], b);

    if (q == 0) {
        atomicAdd(&g_col_r[j], w1);
        atomicAdd(&g_col_d[i], w2);
    }
}

// ---------------------------------------------------------------------------
// Epilogue: per 32-node tile, compute result node-major, transpose through
// shared memory, write out [B, N] coalesced (float4 along v).
// ---------------------------------------------------------------------------
__global__ void final_kernel(const float* __restrict__ bias_r,
                             const float* __restrict__ bias_d,
                             float* __restrict__ out) {
    __shared__ float s[32 * 65];
    int V0 = blockIdx.x * 32;
    int tid = threadIdx.x;      // 0..511

    // compute phase: vl = node within tile, q = 4-batch chunk
    int vl = tid >> 4;
    int q  = tid & 15;
    int v  = V0 + vl;
    if (v < N_NODES) {
        const float4* xt4 = reinterpret_cast<const float4*>(g_xt);
        float4 xv = xt4[v * 16 + q];
        float4 mr = reinterpret_cast<const float4*>(g_msg_r)[v * 16 + q];
        float4 md = reinterpret_cast<const float4*>(g_msg_d)[v * 16 + q];
        float cr = g_col_r[v];
        float cd = g_col_d[v];
        float b1 = bias_r[v];
        float b2 = bias_d[v];

        float xs[4] = {xv.x, xv.y, xv.z, xv.w};
        float ms[4] = {mr.x, mr.y, mr.z, mr.w};
        float dd[4] = {md.x, md.y, md.z, md.w};
        #pragma unroll
        for (int k = 0; k < 4; k++) {
            float reac = cr * xs[k] - ms[k] + b1;
            float diff = cd * xs[k] - dd[k] + b2;
            float res = tanhf(reac) + diff + xs[k];
            s[vl * 65 + q * 4 + k] = res;
        }
    }
    __syncthreads();

    // write phase: b = batch, vg selects 4 consecutive nodes
    int b  = tid >> 3;   // 0..63
    int vg = tid & 7;    // 0..7
    int vbase = V0 + vg * 4;
    if (vbase + 3 < N_NODES) {
        float4 o;
        o.x = s[(vg * 4 + 0) * 65 + b];
        o.y = s[(vg * 4 + 1) * 65 + b];
        o.z = s[(vg * 4 + 2) * 65 + b];
        o.w = s[(vg * 4 + 3) * 65 + b];
        reinterpret_cast<float4*>(out)[((long)b * N_NODES + vbase) >> 2] = o;
    } else if (vbase < N_NODES) {
        for (int k = 0; k < 4 && vbase + k < N_NODES; k++)
            out[(long)b * N_NODES + vbase + k] = s[(vg * 4 + k) * 65 + b];
    }
}

// ---------------------------------------------------------------------------
extern "C" void kernel_launch(void* const* d_in, const int* in_sizes, int n_in,
                              void* d_out, int out_size) {
    // metadata order: t, input, edge_i, edge_j, weight_react, weight_diff,
    //                 bias_reaction, bias_diffusion
    const float* x  = (const float*)d_in[1];
    const int*   ei = (const int*)d_in[2];
    const int*   ej = (const int*)d_in[3];
    const float* wr = (const float*)d_in[4];
    const float* wd = (const float*)d_in[5];
    const float* br = (const float*)d_in[6];
    const float* bd = (const float*)d_in[7];
    float* out = (float*)d_out;

    int zero_threads = 2 * (NB / 4) + 2 * N_NODES;
    zero_kernel<<<(zero_threads + 255) / 256, 256>>>();

    dim3 tg((N_NODES + 31) / 32, B_BATCH / 32);
    transpose_kernel<<<tg, dim3(32, 8)>>>(x);

    long edge_threads = (long)E_EDGES * 16;
    edge_kernel<<<(unsigned)((edge_threads + 255) / 256), 256>>>(ei, ej, wr, wd);

    final_kernel<<<(N_NODES + 31) / 32, 512>>>(br, bd, out);
}